// round 13
// baseline (speedup 1.0000x reference)
#include <cuda_runtime.h>
#include <cuda_bf16.h>
#include <math.h>

#define N_NODES 100000
#define N_EDGES 3200000
#define N_FEAT  512
#define HIDDEN  16
#define SCAN_BLOCKS 98   // ceil(100000/1024)

// ---- scratch (device globals; no runtime allocation) ----
__device__ __nv_bfloat16 d_g[(size_t)N_NODES * HIDDEN];  // bf16: dinv[n]*(x[n]@W1)
__device__ int      d_deg[N_NODES];
__device__ float    d_dinv[N_NODES];
__device__ float    d_csrc[N_NODES];               // sum over out-edges of dinv[dst]
__device__ float    d_s[HIDDEN];                   // sum_n c[n] * r[n]
__device__ int      d_rowstart[N_NODES + 1];       // CSR row starts (by dst)
__device__ int      d_cursor[N_NODES];             // fill cursors
__device__ int      d_esrc[N_EDGES];               // CSR: src of each in-edge
__device__ int      d_bsum[SCAN_BLOCKS];
__device__ unsigned d_done;                        // last-block counter

// ---- PTX helpers ----
__device__ __forceinline__ unsigned f2tf32(float f) {
    unsigned u;
    asm("cvt.rna.tf32.f32 %0, %1;" : "=r"(u) : "f"(f));
    return u;
}
__device__ __forceinline__ void mma_tf32(float d[4], const unsigned a[4], unsigned b0, unsigned b1) {
    asm volatile(
        "mma.sync.aligned.m16n8k8.row.col.f32.tf32.tf32.f32 "
        "{%0,%1,%2,%3}, {%4,%5,%6,%7}, {%8,%9}, {%0,%1,%2,%3};"
        : "+f"(d[0]), "+f"(d[1]), "+f"(d[2]), "+f"(d[3])
        : "r"(a[0]), "r"(a[1]), "r"(a[2]), "r"(a[3]), "r"(b0), "r"(b1));
}
// accumulate 8 bf16 (one float4 worth) into 8 floats
__device__ __forceinline__ void acc8(float* a, float4 v) {
    const __nv_bfloat162* p = (const __nv_bfloat162*)&v;
#pragma unroll
    for (int i = 0; i < 4; i++) {
        float2 t = __bfloat1622float2(p[i]);
        a[2 * i] += t.x;
        a[2 * i + 1] += t.y;
    }
}

// ---- K0: zero scratch ----
__global__ void zero_kernel() {
    int i = blockIdx.x * blockDim.x + threadIdx.x;
    if (i < N_NODES) { d_deg[i] = 0; d_csrc[i] = 0.f; }
    if (i < HIDDEN)  { d_s[i] = 0.f; }
    if (i == 0)      { d_done = 0u; }
}

// ---- K1: in-degree histogram over dst (4 edges/thread) ----
__global__ void hist_kernel(const int4* __restrict__ dst4) {
    int i = blockIdx.x * blockDim.x + threadIdx.x;
    if (i < N_EDGES / 4) {
        int4 d = dst4[i];
        atomicAdd(&d_deg[d.x], 1);
        atomicAdd(&d_deg[d.y], 1);
        atomicAdd(&d_deg[d.z], 1);
        atomicAdd(&d_deg[d.w], 1);
    }
}

// ---- K2: per-block exclusive scan of deg + dinv (1024/block) ----
__global__ void scan1_kernel() {
    __shared__ int sh[1024];
    int t = threadIdx.x;
    int i = blockIdx.x * 1024 + t;
    int v = (i < N_NODES) ? d_deg[i] : 0;
    if (i < N_NODES) d_dinv[i] = rsqrtf((float)(v + 1));   // self-loop included
    sh[t] = v;
    __syncthreads();
#pragma unroll
    for (int off = 1; off < 1024; off <<= 1) {
        int add = (t >= off) ? sh[t - off] : 0;
        __syncthreads();
        sh[t] += add;
        __syncthreads();
    }
    int incl = sh[t];
    if (i < N_NODES) d_rowstart[i] = incl - v;      // exclusive within block
    if (t == 1023) d_bsum[blockIdx.x] = incl;       // block total
}

// ---- K3: fused block-offset scan + apply + cursor init + sentinel ----
__global__ void scan23_kernel() {
    __shared__ int sb[128];
    int t = threadIdx.x;
    if (t < 128) sb[t] = (t < SCAN_BLOCKS) ? d_bsum[t] : 0;
    __syncthreads();
#pragma unroll
    for (int off = 1; off < 128; off <<= 1) {
        int add = (t < 128 && t >= off) ? sb[t - off] : 0;
        __syncthreads();
        if (t < 128) sb[t] += add;
        __syncthreads();
    }
    int boff = (blockIdx.x > 0) ? sb[blockIdx.x - 1] : 0;   // exclusive offset
    int i = blockIdx.x * 1024 + t;
    if (i < N_NODES) {
        int r = d_rowstart[i] + boff;
        d_rowstart[i] = r;
        d_cursor[i] = r;
    }
    if (i == 0) d_rowstart[N_NODES] = N_EDGES;
}

// ---- K4: fill CSR + csrc (4 edges/thread) ----
__global__ void fill_kernel(const int4* __restrict__ src4, const int4* __restrict__ dst4) {
    int i = blockIdx.x * blockDim.x + threadIdx.x;
    if (i >= N_EDGES / 4) return;
    int4 s4 = src4[i];
    int4 d4 = dst4[i];
#pragma unroll
    for (int u = 0; u < 4; u++) {
        int s = (u == 0) ? s4.x : (u == 1) ? s4.y : (u == 2) ? s4.z : s4.w;
        int d = (u == 0) ? d4.x : (u == 1) ? d4.y : (u == 2) ? d4.z : d4.w;
        int slot = atomicAdd(&d_cursor[d], 1);
        d_esrc[slot] = s;
        atomicAdd(&d_csrc[s], d_dinv[d]);
    }
}

// ---- K5: g = dinv * (x @ W1), tf32 MMA, split-W, k-permuted coalesced loads ----
// Depends only on x, W1, d_deg (epilogue computes dinv inline) -> forks after hist.
__global__ __launch_bounds__(256) void gemm_kernel(
    const float* __restrict__ x, const float* __restrict__ W1)
{
    extern __shared__ unsigned dynsmem[];
    unsigned* sWhi = dynsmem;           // [64 ksteps][32 lanes][4] = 8192 u32
    unsigned* sWlo = dynsmem + 8192;

    for (int i = threadIdx.x; i < 8192; i += 256) {
        int s    = i & 3;               // 0=b0n0 1=b1n0 2=b0n1 3=b1n1
        int lane = (i >> 2) & 31;
        int ks   = i >> 7;
        int tig  = lane & 3;
        int gid  = lane >> 2;
        int col_k = (ks >> 1) * 16 + 4 * tig + (ks & 1) * 2 + (s & 1);
        int col_n = (s >> 1) * 8 + gid;
        float w = W1[col_k * 16 + col_n];
        unsigned hi = f2tf32(w);
        float lof = w - __uint_as_float(hi);
        sWhi[i] = hi;
        sWlo[i] = f2tf32(lof);
    }
    __syncthreads();

    int lane = threadIdx.x & 31;
    int warp = threadIdx.x >> 5;
    int tig = lane & 3;
    int gid = lane >> 2;
    int node0 = (blockIdx.x * 8 + warp) * 32;
    if (node0 >= N_NODES) return;

    const float* pr = x + (size_t)(node0 + gid) * N_FEAT;
    const size_t R8 = (size_t)8 * N_FEAT;

    float acc[2][2][4];
#pragma unroll
    for (int mt = 0; mt < 2; mt++)
#pragma unroll
        for (int nt = 0; nt < 2; nt++)
#pragma unroll
            for (int r = 0; r < 4; r++) acc[mt][nt][r] = 0.f;

#pragma unroll 2
    for (int kc = 0; kc < 32; kc++) {
        int cb = kc * 16 + 4 * tig;
        float4 xa = *(const float4*)(pr + cb);
        float4 xb = *(const float4*)(pr + R8 + cb);
        float4 xc = *(const float4*)(pr + 2 * R8 + cb);
        float4 xd = *(const float4*)(pr + 3 * R8 + cb);

        uint4 bh0 = ((const uint4*)sWhi)[(2 * kc) * 32 + lane];
        uint4 bl0 = ((const uint4*)sWlo)[(2 * kc) * 32 + lane];
        uint4 bh1 = ((const uint4*)sWhi)[(2 * kc + 1) * 32 + lane];
        uint4 bl1 = ((const uint4*)sWlo)[(2 * kc + 1) * 32 + lane];

        unsigned a0[4] = { f2tf32(xa.x), f2tf32(xb.x), f2tf32(xa.y), f2tf32(xb.y) };
        unsigned a1[4] = { f2tf32(xc.x), f2tf32(xd.x), f2tf32(xc.y), f2tf32(xd.y) };
        mma_tf32(acc[0][0], a0, bh0.x, bh0.y);
        mma_tf32(acc[0][1], a0, bh0.z, bh0.w);
        mma_tf32(acc[1][0], a1, bh0.x, bh0.y);
        mma_tf32(acc[1][1], a1, bh0.z, bh0.w);
        mma_tf32(acc[0][0], a0, bl0.x, bl0.y);
        mma_tf32(acc[0][1], a0, bl0.z, bl0.w);
        mma_tf32(acc[1][0], a1, bl0.x, bl0.y);
        mma_tf32(acc[1][1], a1, bl0.z, bl0.w);

        unsigned c0[4] = { f2tf32(xa.z), f2tf32(xb.z), f2tf32(xa.w), f2tf32(xb.w) };
        unsigned c1[4] = { f2tf32(xc.z), f2tf32(xd.z), f2tf32(xc.w), f2tf32(xd.w) };
        mma_tf32(acc[0][0], c0, bh1.x, bh1.y);
        mma_tf32(acc[0][1], c0, bh1.z, bh1.w);
        mma_tf32(acc[1][0], c1, bh1.x, bh1.y);
        mma_tf32(acc[1][1], c1, bh1.z, bh1.w);
        mma_tf32(acc[0][0], c0, bl1.x, bl1.y);
        mma_tf32(acc[0][1], c0, bl1.z, bl1.w);
        mma_tf32(acc[1][0], c1, bl1.x, bl1.y);
        mma_tf32(acc[1][1], c1, bl1.z, bl1.w);
    }

    // epilogue: dinv from deg (no scan1 dependency), store bf16 pairs
#pragma unroll
    for (int mt = 0; mt < 2; mt++) {
        int rlo = node0 + mt * 16 + gid;
        int rhi = rlo + 8;
        float dvl = rsqrtf((float)(d_deg[rlo] + 1));
        float dvh = rsqrtf((float)(d_deg[rhi] + 1));
#pragma unroll
        for (int nt = 0; nt < 2; nt++) {
            int col = nt * 8 + 2 * tig;
            *(__nv_bfloat162*)(d_g + (size_t)rlo * HIDDEN + col) =
                __floats2bfloat162_rn(acc[mt][nt][0] * dvl, acc[mt][nt][1] * dvl);
            *(__nv_bfloat162*)(d_g + (size_t)rhi * HIDDEN + col) =
                __floats2bfloat162_rn(acc[mt][nt][2] * dvh, acc[mt][nt][3] * dvh);
        }
    }
}

// ---- K6: fused CSR aggregate + finalize + global reduce + (last block) softmax ----
// 2 lanes per node (h = feature half, 16B = 8 bf16 each); warp spans 16 nodes.
__global__ __launch_bounds__(256) void aggfin_kernel(
    const float* __restrict__ b1, const float* __restrict__ W2,
    const float* __restrict__ b2, float* __restrict__ out)
{
    int tid = threadIdx.x;
    int h = tid & 1;
    int node = blockIdx.x * 128 + (tid >> 1);

    float cr[8];
#pragma unroll
    for (int j = 0; j < 8; j++) cr[j] = 0.f;

    if (node < N_NODES) {
        const float4* gb = (const float4*)d_g;    // row = 2 float4 (16 bf16)
        int beg = d_rowstart[node];
        int end = d_rowstart[node + 1];
        float a[8], b[8];
#pragma unroll
        for (int j = 0; j < 8; j++) { a[j] = 0.f; b[j] = 0.f; }
        int j = beg;
        for (; j + 2 <= end; j += 2) {
            int s0 = d_esrc[j];
            int s1 = d_esrc[j + 1];
            float4 v0 = gb[(size_t)s0 * 2 + h];
            float4 v1 = gb[(size_t)s1 * 2 + h];
            acc8(a, v0);
            acc8(b, v1);
        }
        if (j < end) {
            int s0 = d_esrc[j];
            acc8(a, gb[(size_t)s0 * 2 + h]);
        }
        // self-loop (g already scaled by dinv[node])
        acc8(a, gb[(size_t)node * 2 + h]);
#pragma unroll
        for (int q = 0; q < 8; q++) a[q] += b[q];

        float dv = d_dinv[node];
        float c = dv * (dv + d_csrc[node]);
        const float4* b4 = (const float4*)b1;
        float4 p0 = b4[h * 2], p1 = b4[h * 2 + 1];
        cr[0] = c * fmaxf(fmaf(dv, a[0], p0.x), 0.f);
        cr[1] = c * fmaxf(fmaf(dv, a[1], p0.y), 0.f);
        cr[2] = c * fmaxf(fmaf(dv, a[2], p0.z), 0.f);
        cr[3] = c * fmaxf(fmaf(dv, a[3], p0.w), 0.f);
        cr[4] = c * fmaxf(fmaf(dv, a[4], p1.x), 0.f);
        cr[5] = c * fmaxf(fmaf(dv, a[5], p1.y), 0.f);
        cr[6] = c * fmaxf(fmaf(dv, a[6], p1.z), 0.f);
        cr[7] = c * fmaxf(fmaf(dv, a[7], p1.w), 0.f);
    }

    // reduce across the 16 nodes in the warp (same-parity lanes)
#pragma unroll
    for (int j = 0; j < 8; j++) {
        float v = cr[j];
#pragma unroll
        for (int off = 2; off <= 16; off <<= 1)
            v += __shfl_xor_sync(0xffffffffu, v, off);
        cr[j] = v;
    }

    __shared__ float red[8][HIDDEN];
    __shared__ int sh_last;
    if (tid == 0) sh_last = 0;
    int lane = tid & 31;
    int w = tid >> 5;
    if (lane < 2) {
#pragma unroll
        for (int j = 0; j < 8; j++) red[w][lane * 8 + j] = cr[j];
    }
    __syncthreads();
    if (tid < HIDDEN) {
        float t = 0.f;
#pragma unroll
        for (int ww = 0; ww < 8; ww++) t += red[ww][tid];
        atomicAdd(&d_s[tid], t);
    }

    // last-block: compute pooled logits + softmax
    __syncthreads();
    if (tid == 0) {
        __threadfence();
        unsigned r = atomicAdd(&d_done, 1u);
        sh_last = (r == gridDim.x - 1) ? 1 : 0;
    }
    __syncthreads();
    if (sh_last && tid < 32) {
        // ALL 32 lanes execute this block convergently — shfl is well-defined.
        int k = tid;
        int kc = (k < HIDDEN) ? k : 0;           // clamp for safe W2 indexing
        __threadfence();                          // acquire: order d_s reads after d_done
        float sk = (k < HIDDEN) ? __ldcg(&d_s[k]) : 0.f;  // L1-bypass read of L2 atomics
        float acc = 0.f;
#pragma unroll
        for (int jj = 0; jj < HIDDEN; jj++) {
            float sj = __shfl_sync(0xffffffffu, sk, jj);   // converged: no divergence UB
            acc += sj * W2[jj * HIDDEN + kc];
        }
        float p = (k < HIDDEN) ? (acc * (1.0f / (float)N_NODES) + b2[kc]) : -INFINITY;
        float m = p;
#pragma unroll
        for (int off = 16; off > 0; off >>= 1)
            m = fmaxf(m, __shfl_xor_sync(0xffffffffu, m, off));
        float e = (k < HIDDEN) ? expf(p - m) : 0.f;
        float ssum = e;
#pragma unroll
        for (int off = 16; off > 0; off >>= 1)
            ssum += __shfl_xor_sync(0xffffffffu, ssum, off);
        if (k < HIDDEN) out[k] = e / ssum;
    }
}

extern "C" void kernel_launch(void* const* d_in, const int* in_sizes, int n_in,
                              void* d_out, int out_size)
{
    const float* x  = (const float*)d_in[0];
    const int*   ei = (const int*)d_in[1];     // [2, E] row-major
    const float* W1 = (const float*)d_in[2];
    const float* b1 = (const float*)d_in[3];
    const float* W2 = (const float*)d_in[4];
    const float* b2 = (const float*)d_in[5];
    const int* src = ei;
    const int* dst = ei + N_EDGES;
    float* out = (float*)d_out;

    cudaFuncSetAttribute(gemm_kernel, cudaFuncAttributeMaxDynamicSharedMemorySize,
                         2 * 8192 * sizeof(unsigned));

    // fork/join side stream for the GEMM (host-side handles only; no device mem)
    cudaStream_t s2;
    cudaStreamCreateWithFlags(&s2, cudaStreamNonBlocking);
    cudaEvent_t evFork, evJoin;
    cudaEventCreateWithFlags(&evFork, cudaEventDisableTiming);
    cudaEventCreateWithFlags(&evJoin, cudaEventDisableTiming);

    // main stream: edge pipeline
    zero_kernel<<<(N_NODES + 255) / 256, 256>>>();
    hist_kernel<<<((N_EDGES / 4) + 255) / 256, 256>>>((const int4*)dst);
    cudaEventRecord(evFork, 0);                       // deg ready

    // side stream: GEMM (reads x, W1, d_deg; writes d_g)
    cudaStreamWaitEvent(s2, evFork, 0);
    gemm_kernel<<<(N_NODES + 255) / 256, 256, 2 * 8192 * sizeof(unsigned), s2>>>(x, W1);
    cudaEventRecord(evJoin, s2);

    // main stream continues: CSR build
    scan1_kernel<<<SCAN_BLOCKS, 1024>>>();
    scan23_kernel<<<SCAN_BLOCKS, 1024>>>();
    fill_kernel<<<((N_EDGES / 4) + 255) / 256, 256>>>((const int4*)src, (const int4*)dst);

    // join: aggregation needs d_g
    cudaStreamWaitEvent(0, evJoin, 0);
    aggfin_kernel<<<(N_NODES + 127) / 128, 256>>>(b1, W2, b2, out);
}